// round 13
// baseline (speedup 1.0000x reference)
#include <cuda_runtime.h>
#include <math_constants.h>

// x[B=4, C=256, H=200, W=320] f32 -> out[B,H,W] f32
#define Bn 4
#define Cn 256
#define Hn 200
#define Wn 320
#define HWn (Hn * Wn)        // 64000
#define HW4 (HWn / 4)        // 16000 float4/plane
#define NPIX (Bn * HWn)      // 256000
#define GW (Wn / 4)          // 80 groups/row

#define NEG_INF (-CUDART_INF_F)

__device__ float4 g_pD[4 * Bn * HW4];   // 4 MB: per-chunk partial depth max
__device__ float  g_D[NPIX];            // 1 MB: depthwise max

__device__ __forceinline__ float4 f4max(float4 a, float4 b) {
    return make_float4(fmaxf(a.x, b.x), fmaxf(a.y, b.y),
                       fmaxf(a.z, b.z), fmaxf(a.w, b.w));
}

// ---- K1a: partial depthwise max over 64-channel chunk (pure fmax) ----------
__global__ void __launch_bounds__(256)
dmax_partial_kernel(const float* __restrict__ x) {
    const int g = blockIdx.x * 256 + threadIdx.x;   // 0..Bn*HW4-1 exact
    const int chunk = blockIdx.y;                   // 0..3
    const int b  = g / HW4;
    const int pg = g - b * HW4;

    const float4* __restrict__ src = reinterpret_cast<const float4*>(x)
        + (size_t)(b * Cn + chunk * 64) * HW4 + pg;

    float4 a0 = make_float4(NEG_INF, NEG_INF, NEG_INF, NEG_INF);
    float4 a1 = a0, a2 = a0, a3 = a0;
#pragma unroll 4
    for (int c = 0; c < 64; c += 16) {
        float4 v[16];
#pragma unroll
        for (int j = 0; j < 16; ++j) v[j] = __ldg(src + (size_t)(c + j) * HW4);
#pragma unroll
        for (int j = 0; j < 16; j += 4) {
            a0 = f4max(a0, v[j + 0]);
            a1 = f4max(a1, v[j + 1]);
            a2 = f4max(a2, v[j + 2]);
            a3 = f4max(a3, v[j + 3]);
        }
    }
    g_pD[(size_t)chunk * (Bn * HW4) + g] = f4max(f4max(a0, a1), f4max(a2, a3));
}

// ---- K1b: merge 4 partials -> g_D; zero the output ------------------------
__global__ void __launch_bounds__(256)
dmax_merge_kernel(float* __restrict__ out) {
    const int g = blockIdx.x * 256 + threadIdx.x;   // 0..Bn*HW4-1 exact
    float4 m = f4max(f4max(g_pD[g], g_pD[Bn * HW4 + g]),
                     f4max(g_pD[2 * Bn * HW4 + g], g_pD[3 * Bn * HW4 + g]));
    reinterpret_cast<float4*>(g_D)[g] = m;
    reinterpret_cast<float4*>(out)[g] = make_float4(0.f, 0.f, 0.f, 0.f);
}

// ---- K2: dense separable 9x9 windowmax; overlapping loads, no shfl/sync ----
// Block = 2 (b,c) planes, 160 threads (5 full warps). Thread owns 4 output
// columns of one channel; per row loads left/mid/right float4 (12-wide span).
// Horizontal 9-max = 15 fmax from the span; vertical 9-max via register rings.
// Batch-4 rows: 12 row LDGs + 4 D LDGs issued up front (high MLP, no MIO).
__global__ void __launch_bounds__(160)
sweep_kernel(const float* __restrict__ x, float* __restrict__ out) {
    const int tid  = threadIdx.x;
    const int half = (tid >= 80) ? 1 : 0;
    const int g    = tid - half * 80;         // output group 0..79
    const int bc   = blockIdx.x;              // 0..511
    const int b    = bc >> 7;
    const int c    = (bc & 127) * 2 + half;

    const float4* __restrict__ plane4 =
        reinterpret_cast<const float4*>(x) + (size_t)(b * Cn + c) * HW4;
    const float4* __restrict__ D4 =
        reinterpret_cast<const float4*>(g_D) + (size_t)b * HW4;

    const bool hasL = (g > 0);
    const bool hasR = (g < GW - 1);

    const float4 NEG4 = make_float4(NEG_INF, NEG_INF, NEG_INF, NEG_INF);
    float4 hmr[8], m2r[2], m4r[4], vr[4];
#pragma unroll
    for (int i = 0; i < 8; ++i) hmr[i] = NEG4;
    m2r[0] = m2r[1] = NEG4;
    m4r[0] = m4r[1] = m4r[2] = m4r[3] = NEG4;
    vr[0] = vr[1] = vr[2] = vr[3] = NEG4;

    for (int it = 0; it < 52; ++it) {
        // ---- front-batched loads: 4 rows x {L,M,R} + 4 D rows ----
        float4 L[4], M[4], R[4], dv[4];
#pragma unroll
        for (int u = 0; u < 4; ++u) {
            int ly = 4 * it + u - 4;
            ly = ly < 0 ? 0 : (ly > Hn - 1 ? Hn - 1 : ly);   // clamp: max-safe
            const float4* rowp = plane4 + ly * GW + g;
            M[u] = __ldg(rowp);
            L[u] = hasL ? __ldg(rowp - 1) : NEG4;
            R[u] = hasR ? __ldg(rowp + 1) : NEG4;
        }
#pragma unroll
        for (int u = 0; u < 4; ++u) {
            const int j = 4 * it + u - 8;              // center row this step
            dv[u] = (j >= 0) ? __ldg(D4 + j * GW + g) : NEG4;
        }

#pragma unroll
        for (int u = 0; u < 4; ++u) {
            const int i = 4 * it + u;
            const float4 l = L[u], m = M[u], r = R[u];

            // horizontal 9-max from 12-span (v0..v3=l, v4..v7=m, v8..v11=r)
            const float mmid = fmaxf(fmaxf(m.x, m.y), fmaxf(m.z, m.w)); // v4..7
            const float c38  = fmaxf(l.w, fmaxf(mmid, r.x));            // v3..8
            const float s12  = fmaxf(l.y, l.z);                         // v1,v2
            const float p910 = fmaxf(r.y, r.z);                         // v9,v10
            const float p911 = fmaxf(p910, r.w);                        // v9..11
            float4 hm;
            hm.x = fmaxf(c38, fmaxf(l.x, s12));    // v0..v8
            hm.y = fmaxf(c38, fmaxf(s12, r.y));    // v1..v9
            hm.z = fmaxf(c38, fmaxf(l.z, p910));   // v2..v10
            hm.w = fmaxf(c38, p911);               // v3..v11
            // (l/r are NEG_INF at image edges; clamped rows duplicate: max-safe)

            // vertical 9-max rings (read-before-write)
            const float4 hm8 = hmr[i & 7];                    // hm(i-8)
            const float4 m2  = f4max(hm, hmr[(i + 7) & 7]);   // {i-1, i}
            const float4 m4  = f4max(m2, m2r[i & 1]);         // {i-3..i}
            const float4 m8  = f4max(m4, m4r[i & 3]);         // {i-7..i}
            hmr[i & 7] = hm;
            m2r[i & 1] = m2;
            m4r[i & 3] = m4;
            const float4 win = f4max(m8, hm8);                // rows j-4..j+4

            // vc = x at plane row j = i-8 (mid loaded 4 iterations ago)
            const float4 vc = vr[i & 3];
            vr[i & 3] = m;

            if (i >= 8) {
                const int j = i - 8;
                const float4 dvv = dv[u];
                const int pbase = b * HWn + j * Wn + g * 4;
                // win >= vc always (window includes center): pass <=> ==
                if (vc.x == dvv.x && win.x <= vc.x) atomicAdd(out + pbase + 0, vc.x);
                if (vc.y == dvv.y && win.y <= vc.y) atomicAdd(out + pbase + 1, vc.y);
                if (vc.z == dvv.z && win.z <= vc.z) atomicAdd(out + pbase + 2, vc.z);
                if (vc.w == dvv.w && win.w <= vc.w) atomicAdd(out + pbase + 3, vc.w);
            }
        }
    }
}

extern "C" void kernel_launch(void* const* d_in, const int* in_sizes, int n_in,
                              void* d_out, int out_size) {
    const float* x = (const float*)d_in[0];
    float* out = (float*)d_out;
    (void)in_sizes; (void)n_in; (void)out_size;

    dim3 gA((Bn * HW4) / 256, 4);
    dmax_partial_kernel<<<gA, 256>>>(x);               // 250x4 blocks
    dmax_merge_kernel<<<(Bn * HW4) / 256, 256>>>(out); // 250 blocks
    sweep_kernel<<<(Bn * Cn) / 2, 160>>>(x, out);      // 512 blocks
}

// round 14
// speedup vs baseline: 1.0807x; 1.0807x over previous
#include <cuda_runtime.h>
#include <math_constants.h>

// x[B=4, C=256, H=200, W=320] f32 -> out[B,H,W] f32
#define Bn 4
#define Cn 256
#define Hn 200
#define Wn 320
#define HWn (Hn * Wn)        // 64000
#define HW4 (HWn / 4)        // 16000 float4/plane
#define NPIX (Bn * HWn)      // 256000
#define GW (Wn / 4)          // 80 groups/row

#define NEG_INF (-CUDART_INF_F)

__device__ float4 g_pD[4 * Bn * HW4];   // 4 MB: per-chunk partial depth max
__device__ float  g_D[NPIX];            // 1 MB: depthwise max

__device__ __forceinline__ float4 f4max(float4 a, float4 b) {
    return make_float4(fmaxf(a.x, b.x), fmaxf(a.y, b.y),
                       fmaxf(a.z, b.z), fmaxf(a.w, b.w));
}

// ---- K1a: partial depthwise max over 64-channel chunk (pure fmax) ----------
__global__ void __launch_bounds__(256)
dmax_partial_kernel(const float* __restrict__ x) {
    const int g = blockIdx.x * 256 + threadIdx.x;   // 0..Bn*HW4-1 exact
    const int chunk = blockIdx.y;                   // 0..3
    const int b  = g / HW4;
    const int pg = g - b * HW4;

    const float4* __restrict__ src = reinterpret_cast<const float4*>(x)
        + (size_t)(b * Cn + chunk * 64) * HW4 + pg;

    float4 a0 = make_float4(NEG_INF, NEG_INF, NEG_INF, NEG_INF);
    float4 a1 = a0, a2 = a0, a3 = a0;
#pragma unroll 4
    for (int c = 0; c < 64; c += 16) {
        float4 v[16];
#pragma unroll
        for (int j = 0; j < 16; ++j) v[j] = __ldg(src + (size_t)(c + j) * HW4);
#pragma unroll
        for (int j = 0; j < 16; j += 4) {
            a0 = f4max(a0, v[j + 0]);
            a1 = f4max(a1, v[j + 1]);
            a2 = f4max(a2, v[j + 2]);
            a3 = f4max(a3, v[j + 3]);
        }
    }
    g_pD[(size_t)chunk * (Bn * HW4) + g] = f4max(f4max(a0, a1), f4max(a2, a3));
}

// ---- K1b: merge 4 partials -> g_D; zero the output ------------------------
__global__ void __launch_bounds__(256)
dmax_merge_kernel(float* __restrict__ out) {
    const int g = blockIdx.x * 256 + threadIdx.x;   // 0..Bn*HW4-1 exact
    float4 m = f4max(f4max(g_pD[g], g_pD[Bn * HW4 + g]),
                     f4max(g_pD[2 * Bn * HW4 + g], g_pD[3 * Bn * HW4 + g]));
    reinterpret_cast<float4*>(g_D)[g] = m;
    reinterpret_cast<float4*>(out)[g] = make_float4(0.f, 0.f, 0.f, 0.f);
}

// ---- K2: dense separable 9x9 windowmax; batch-8 MLP, shfl halos, half-planes
// Block = one (b,c) half-plane (100 output rows). 128 threads = 4 warps;
// warp w: lanes 0..19 own output groups 20w..20w+19, lane 20/21 load halos.
// Batch-8 row loads front-issued; D row prefetched 1 row ahead (L2-resident);
// center values via 4-deep register ring. No smem, no syncs.
__global__ void __launch_bounds__(128)
sweep_kernel(const float* __restrict__ x, float* __restrict__ out) {
    const int tid  = threadIdx.x;
    const int wid  = tid >> 5;
    const int lane = tid & 31;
    const int bcx  = blockIdx.x;            // 0..2047
    const int half = bcx & 1;
    const int c    = (bcx >> 1) & (Cn - 1);
    const int b    = bcx >> 9;

    const int i0  = half * 96;              // first step index
    const int jlo = half * 100;             // emit rows [jlo, jhi)
    const int jhi = jlo + 100;

    const bool outlane = lane < 20;
    int ldgx;
    if (lane < 20)       ldgx = wid * 20 + lane;
    else if (lane == 20) ldgx = wid * 20 - 1;        // left halo
    else if (lane == 21) ldgx = wid * 20 + 20;       // right halo
    else                 ldgx = -1;
    const bool ldvalid = (ldgx >= 0) && (ldgx < GW);
    const int gx = wid * 20 + lane;                  // output group (lanes<20)
    const int srcL = (lane == 0)  ? 20 : lane - 1;
    const int srcR = (lane == 19) ? 21 : lane + 1;

    const float4* __restrict__ plane4 =
        reinterpret_cast<const float4*>(x) + (size_t)(b * Cn + c) * HW4;
    const float4* __restrict__ D4 =
        reinterpret_cast<const float4*>(g_D) + (size_t)b * HW4;

    const float4 NEG4 = make_float4(NEG_INF, NEG_INF, NEG_INF, NEG_INF);
    float4 hmr[8], m2r[2], m4r[4], vr[4];
#pragma unroll
    for (int i = 0; i < 8; ++i) hmr[i] = NEG4;
    m2r[0] = m2r[1] = NEG4;
    m4r[0] = m4r[1] = m4r[2] = m4r[3] = NEG4;
    vr[0] = vr[1] = vr[2] = vr[3] = NEG4;
    float4 dv = NEG4;

    for (int it = 0; it < 14; ++it) {
        // ---- front-batched row loads (8 independent LDG.128) ----
        float4 va[8];
#pragma unroll
        for (int u = 0; u < 8; ++u) {
            int ly = i0 + 8 * it + u - 4;
            ly = ly < 0 ? 0 : (ly > Hn - 1 ? Hn - 1 : ly);  // clamp: max-safe
            va[u] = ldvalid ? __ldg(plane4 + ly * GW + ldgx) : NEG4;
        }

#pragma unroll
        for (int u = 0; u < 8; ++u) {
            const int i = i0 + 8 * it + u;
            const float4 v = va[u];
            // own prefixes/suffixes
            const float p1 = fmaxf(v.x, v.y);
            const float p2 = fmaxf(p1, v.z);
            const float p3 = fmaxf(p2, v.w);
            const float s3 = v.w;
            const float s2 = fmaxf(v.z, s3);
            const float s1 = fmaxf(v.y, s2);
            // halo exchange (uniform shfl.idx, full warp)
            const float ls0 = __shfl_sync(0xFFFFFFFFu, p3,  srcL);
            const float ls1 = __shfl_sync(0xFFFFFFFFu, s1,  srcL);
            const float ls2 = __shfl_sync(0xFFFFFFFFu, s2,  srcL);
            const float ls3 = __shfl_sync(0xFFFFFFFFu, s3,  srcL);
            const float rp0 = __shfl_sync(0xFFFFFFFFu, v.x, srcR);
            const float rp1 = __shfl_sync(0xFFFFFFFFu, p1,  srcR);
            const float rp2 = __shfl_sync(0xFFFFFFFFu, p2,  srcR);
            const float rp3 = __shfl_sync(0xFFFFFFFFu, p3,  srcR);
            // horizontal 9-max
            float4 hm;
            hm.x = fmaxf(ls0, fmaxf(p3, rp0));
            hm.y = fmaxf(ls1, fmaxf(p3, rp1));
            hm.z = fmaxf(ls2, fmaxf(p3, rp2));
            hm.w = fmaxf(ls3, fmaxf(p3, rp3));

            // vertical 9-max rings (read-before-write); hm(step i)=row i-4
            const float4 hm8 = hmr[i & 7];                   // hm(i-8)
            const float4 m2  = f4max(hm, hmr[(i + 7) & 7]);  // steps {i-1,i}
            const float4 m4  = f4max(m2, m2r[i & 1]);        // {i-3..i}
            const float4 m8  = f4max(m4, m4r[i & 3]);        // {i-7..i}
            hmr[i & 7] = hm;
            m2r[i & 1] = m2;
            m4r[i & 3] = m4;
            const float4 win = f4max(m8, hm8);  // rows (i-12..i-4) = j-4..j+4

            // center value ring: vc = row j = i-8 (stored 4 steps ago)
            const float4 vc = vr[i & 3];
            vr[i & 3] = v;

            const int j = i - 8;
            if (outlane && j >= jlo && j < jhi) {
                const int pbase = b * HWn + j * Wn + gx * 4;
                // win >= vc always (window includes center): pass <=> ==
                if (vc.x == dv.x && win.x <= vc.x) atomicAdd(out + pbase + 0, vc.x);
                if (vc.y == dv.y && win.y <= vc.y) atomicAdd(out + pbase + 1, vc.y);
                if (vc.z == dv.z && win.z <= vc.z) atomicAdd(out + pbase + 2, vc.z);
                if (vc.w == dv.w && win.w <= vc.w) atomicAdd(out + pbase + 3, vc.w);
            }
            // prefetch D row for next step (L2-resident)
            const int jn = j + 1;
            if (outlane && jn >= jlo && jn < jhi)
                dv = __ldg(D4 + jn * GW + gx);
        }
    }
}

extern "C" void kernel_launch(void* const* d_in, const int* in_sizes, int n_in,
                              void* d_out, int out_size) {
    const float* x = (const float*)d_in[0];
    float* out = (float*)d_out;
    (void)in_sizes; (void)n_in; (void)out_size;

    dim3 gA((Bn * HW4) / 256, 4);
    dmax_partial_kernel<<<gA, 256>>>(x);               // 250x4 blocks
    dmax_merge_kernel<<<(Bn * HW4) / 256, 256>>>(out); // 250 blocks
    sweep_kernel<<<Bn * Cn * 2, 128>>>(x, out);        // 2048 blocks
}

// round 15
// speedup vs baseline: 1.4715x; 1.3615x over previous
#include <cuda_runtime.h>
#include <math_constants.h>

// x[B=4, C=256, H=200, W=320] f32 -> out[B,H,W] f32
#define Bn 4
#define Cn 256
#define Hn 200
#define Wn 320
#define HWn (Hn * Wn)        // 64000
#define HW4 (HWn / 4)        // 16000 float4/plane
#define NPIX (Bn * HWn)      // 256000
#define GW (Wn / 4)          // 80 groups/row

#define NEG_INF (-CUDART_INF_F)

__device__ float4 g_pD[4 * Bn * HW4];   // 4 MB: per-chunk partial depth max
__device__ float  g_D[NPIX];            // 1 MB: depthwise max

__device__ __forceinline__ float4 f4max(float4 a, float4 b) {
    return make_float4(fmaxf(a.x, b.x), fmaxf(a.y, b.y),
                       fmaxf(a.z, b.z), fmaxf(a.w, b.w));
}

// ---- K1a: partial depthwise max over 64-channel chunk (pure fmax) ----------
__global__ void __launch_bounds__(256)
dmax_partial_kernel(const float* __restrict__ x) {
    const int g = blockIdx.x * 256 + threadIdx.x;   // 0..Bn*HW4-1 exact
    const int chunk = blockIdx.y;                   // 0..3
    const int b  = g / HW4;
    const int pg = g - b * HW4;

    const float4* __restrict__ src = reinterpret_cast<const float4*>(x)
        + (size_t)(b * Cn + chunk * 64) * HW4 + pg;

    float4 a0 = make_float4(NEG_INF, NEG_INF, NEG_INF, NEG_INF);
    float4 a1 = a0, a2 = a0, a3 = a0;
#pragma unroll 4
    for (int c = 0; c < 64; c += 16) {
        float4 v[16];
#pragma unroll
        for (int j = 0; j < 16; ++j) v[j] = __ldg(src + (size_t)(c + j) * HW4);
#pragma unroll
        for (int j = 0; j < 16; j += 4) {
            a0 = f4max(a0, v[j + 0]);
            a1 = f4max(a1, v[j + 1]);
            a2 = f4max(a2, v[j + 2]);
            a3 = f4max(a3, v[j + 3]);
        }
    }
    g_pD[(size_t)chunk * (Bn * HW4) + g] = f4max(f4max(a0, a1), f4max(a2, a3));
}

// ---- K1b: merge 4 partials -> g_D; zero the output ------------------------
__global__ void __launch_bounds__(256)
dmax_merge_kernel(float* __restrict__ out) {
    const int g = blockIdx.x * 256 + threadIdx.x;   // 0..Bn*HW4-1 exact
    float4 m = f4max(f4max(g_pD[g], g_pD[Bn * HW4 + g]),
                     f4max(g_pD[2 * Bn * HW4 + g], g_pD[3 * Bn * HW4 + g]));
    reinterpret_cast<float4*>(g_D)[g] = m;
    reinterpret_cast<float4*>(out)[g] = make_float4(0.f, 0.f, 0.f, 0.f);
}

// ---- K2: dense separable 9x9 windowmax; batch-8 M stream, JIT L1-hit halos
// Block = 2 (b,c) planes, 160 threads (5 full warps, no idle lanes). Thread
// owns 4 output cols of one plane. Per row: M from the front-issued batch of
// 8; L/R neighbor float4s and the D row are prefetched ONE ROW AHEAD with
// unconditional clamped loads (L/R are L1 hits on lines the M-batch of the
// neighboring threads just pulled; D is L2-resident). No shfl, no smem.
__global__ void __launch_bounds__(160, 2)
sweep_kernel(const float* __restrict__ x, float* __restrict__ out) {
    const int tid  = threadIdx.x;
    const int half = (tid >= 80) ? 1 : 0;
    const int g    = tid - half * 80;         // output group 0..79
    const int bc   = blockIdx.x;              // 0..511
    const int b    = bc >> 7;
    const int c    = (bc & 127) * 2 + half;

    const float4* __restrict__ plane4 =
        reinterpret_cast<const float4*>(x) + (size_t)(b * Cn + c) * HW4;
    const float4* __restrict__ D4 =
        reinterpret_cast<const float4*>(g_D) + (size_t)b * HW4;

    const bool hasL = (g > 0);
    const bool hasR = (g < GW - 1);

    const float4 NEG4 = make_float4(NEG_INF, NEG_INF, NEG_INF, NEG_INF);
    float4 hmr[8], m2r[2], m4r[4], vr[4];
#pragma unroll
    for (int i = 0; i < 8; ++i) hmr[i] = NEG4;
    m2r[0] = m2r[1] = NEG4;
    m4r[0] = m4r[1] = m4r[2] = m4r[3] = NEG4;
    vr[0] = vr[1] = vr[2] = vr[3] = NEG4;

    // ---- prime the 1-row-ahead pipeline for step i=0 (row clamp(-4)=0) ----
    float4 Ln = hasL ? __ldg(plane4 + 0 * GW + g - 1) : NEG4;
    float4 Rn = hasR ? __ldg(plane4 + 0 * GW + g + 1) : NEG4;
    float4 dvn = __ldg(D4 + 0 * GW + g);     // j=-8 clamped; unused (no emit)

    for (int it = 0; it < 26; ++it) {
        // ---- front-batched M stream: 8 independent LDG.128 ----
        float4 M[8];
#pragma unroll
        for (int u = 0; u < 8; ++u) {
            int ly = 8 * it + u - 4;
            ly = ly < 0 ? 0 : (ly > Hn - 1 ? Hn - 1 : ly);  // clamp: max-safe
            M[u] = __ldg(plane4 + ly * GW + g);
        }

#pragma unroll
        for (int u = 0; u < 8; ++u) {
            const int i = 8 * it + u;
            const float4 l = Ln, r = Rn, dv = dvn;
            const float4 m = M[u];

            // ---- prefetch L/R/D for next step (unconditional, clamped) ----
            {
                int lyn = i - 3;                       // row of step i+1
                lyn = lyn < 0 ? 0 : (lyn > Hn - 1 ? Hn - 1 : lyn);
                Ln = hasL ? __ldg(plane4 + lyn * GW + g - 1) : NEG4;
                Rn = hasR ? __ldg(plane4 + lyn * GW + g + 1) : NEG4;
                int jn = i - 7;                        // center row of step i+1
                jn = jn < 0 ? 0 : (jn > Hn - 1 ? Hn - 1 : jn);
                dvn = __ldg(D4 + jn * GW + g);
            }

            // horizontal 9-max from 12-span (v0..3=l, v4..7=m, v8..11=r)
            const float mmid = fmaxf(fmaxf(m.x, m.y), fmaxf(m.z, m.w)); // v4..7
            const float c38  = fmaxf(l.w, fmaxf(mmid, r.x));            // v3..8
            const float s12  = fmaxf(l.y, l.z);                         // v1,v2
            const float p910 = fmaxf(r.y, r.z);                         // v9,v10
            const float p911 = fmaxf(p910, r.w);                        // v9..11
            float4 hm;
            hm.x = fmaxf(c38, fmaxf(l.x, s12));    // v0..v8
            hm.y = fmaxf(c38, fmaxf(s12, r.y));    // v1..v9
            hm.z = fmaxf(c38, fmaxf(l.z, p910));   // v2..v10
            hm.w = fmaxf(c38, p911);               // v3..v11

            // vertical 9-max rings (read-before-write); hm(step i)=row i-4
            const float4 hm8 = hmr[u];                       // hm(i-8)
            const float4 m2  = f4max(hm, hmr[(u + 7) & 7]);  // steps {i-1,i}
            const float4 m4  = f4max(m2, m2r[u & 1]);        // {i-3..i}
            const float4 m8  = f4max(m4, m4r[u & 3]);        // {i-7..i}
            hmr[u]     = hm;
            m2r[u & 1] = m2;
            m4r[u & 3] = m4;
            const float4 win = f4max(m8, hm8);   // rows (i-12..i-4) = j-4..j+4

            // center value ring: vc = M from step i-4 = row i-8 = j
            const float4 vc = vr[u & 3];
            vr[u & 3] = m;

            if (it > 0) {                        // uniform branch; j in [0,199]
                const int j = i - 8;
                const int pbase = b * HWn + j * Wn + g * 4;
                // win >= vc always (window includes center): pass <=> ==
                if (vc.x == dv.x && win.x <= vc.x) atomicAdd(out + pbase + 0, vc.x);
                if (vc.y == dv.y && win.y <= vc.y) atomicAdd(out + pbase + 1, vc.y);
                if (vc.z == dv.z && win.z <= vc.z) atomicAdd(out + pbase + 2, vc.z);
                if (vc.w == dv.w && win.w <= vc.w) atomicAdd(out + pbase + 3, vc.w);
            }
        }
    }
}

extern "C" void kernel_launch(void* const* d_in, const int* in_sizes, int n_in,
                              void* d_out, int out_size) {
    const float* x = (const float*)d_in[0];
    float* out = (float*)d_out;
    (void)in_sizes; (void)n_in; (void)out_size;

    dim3 gA((Bn * HW4) / 256, 4);
    dmax_partial_kernel<<<gA, 256>>>(x);               // 250x4 blocks
    dmax_merge_kernel<<<(Bn * HW4) / 256, 256>>>(out); // 250 blocks
    sweep_kernel<<<(Bn * Cn) / 2, 160>>>(x, out);      // 512 blocks
}

// round 16
// speedup vs baseline: 1.5142x; 1.0291x over previous
#include <cuda_runtime.h>
#include <math_constants.h>

// x[B=4, C=256, H=200, W=320] f32 -> out[B,H,W] f32
#define Bn 4
#define Cn 256
#define Hn 200
#define Wn 320
#define HWn (Hn * Wn)            // 64000
#define CHWn (Cn * HWn)          // 16384000
#define HW4 (HWn / 4)            // 16000
#define NPIX (Bn * HWn)          // 256000
#define NGRP (Bn * HW4)          // 64000
#define NBIN (Bn * Cn)           // 1024

#define CHUNKS 4
#define CPC   (Cn / CHUNKS)      // 64

#define NEG_INF (-CUDART_INF_F)

// ---- scratch (device globals) ----
__device__ float4   g_pmax[CHUNKS * NGRP];   // 4 MB
__device__ int4     g_pmeta[CHUNKS * NGRP];  // 4 MB
__device__ float    g_mx[NPIX];              // 1 MB
__device__ unsigned g_amf[NPIX];             // 1 MB
__device__ unsigned g_hist[NBIN];
__device__ unsigned g_cursor[NBIN];
__device__ unsigned g_list[NPIX];            // 1 MB: p | am<<18 | tie<<26

// ---------------- K1: channel-chunk partial depth-wise argmax ----------------
__global__ void __launch_bounds__(256)
phaseA_kernel(const float* __restrict__ x) {
    // Fold hist zeroing into this kernel (block 0); completes before K2 launch.
    if (blockIdx.x == 0) {
#pragma unroll
        for (int i = 0; i < NBIN / 256; ++i)
            g_hist[threadIdx.x + i * 256] = 0;
    }

    const int t = blockIdx.x * 256 + threadIdx.x;   // exact cover
    const int chunk = t / NGRP;
    const int gg    = t - chunk * NGRP;
    const int b     = gg / HW4;
    const int pg    = gg - b * HW4;

    const float4* __restrict__ src =
        reinterpret_cast<const float4*>(x + (size_t)b * CHWn
                                          + (size_t)chunk * CPC * HWn) + pg;

    float mx[4]; int am[4]; int cn[4];
#pragma unroll
    for (int k = 0; k < 4; ++k) { mx[k] = NEG_INF; am[k] = 0; cn[k] = 0; }

#pragma unroll 2
    for (int c0 = 0; c0 < CPC; c0 += 8) {
        float4 v[8];
#pragma unroll
        for (int j = 0; j < 8; ++j)
            v[j] = __ldg(src + (size_t)(c0 + j) * HW4);
#pragma unroll
        for (int j = 0; j < 8; ++j) {
            const float vv[4] = {v[j].x, v[j].y, v[j].z, v[j].w};
#pragma unroll
            for (int k = 0; k < 4; ++k) {
                const bool gt = vv[k] > mx[k];
                const bool eq = vv[k] == mx[k];
                cn[k] = gt ? 1 : (cn[k] + (eq ? 1 : 0));
                am[k] = gt ? (c0 + j) : am[k];
                mx[k] = fmaxf(mx[k], vv[k]);
            }
        }
    }

    g_pmax[t] = make_float4(mx[0], mx[1], mx[2], mx[3]);
    int4 meta;
    meta.x = (chunk * CPC + am[0]) | (cn[0] << 16);
    meta.y = (chunk * CPC + am[1]) | (cn[1] << 16);
    meta.z = (chunk * CPC + am[2]) | (cn[2] << 16);
    meta.w = (chunk * CPC + am[3]) | (cn[3] << 16);
    g_pmeta[t] = meta;
}

// ---------------- K2: merge partials per pixel + histogram -------------------
__global__ void __launch_bounds__(256)
merge_count_kernel() {
    __shared__ unsigned s_cnt[NBIN];
#pragma unroll
    for (int i = 0; i < NBIN / 256; ++i)
        s_cnt[threadIdx.x + i * 256] = 0;
    __syncthreads();

    const int p = blockIdx.x * 256 + threadIdx.x;   // exact cover
    const float* __restrict__ pmax  = reinterpret_cast<const float*>(g_pmax);
    const int*   __restrict__ pmeta = reinterpret_cast<const int*>(g_pmeta);

    float mx = NEG_INF; int am = 0; int cn = 0;
#pragma unroll
    for (int ch = 0; ch < CHUNKS; ++ch) {
        const float m    = pmax[ch * NPIX + p];
        const int   meta = pmeta[ch * NPIX + p];
        const bool gt = m > mx;
        const bool eq = m == mx;
        cn = gt ? (meta >> 16) : (cn + (eq ? (meta >> 16) : 0));
        am = gt ? (meta & 0xFFFF) : am;
        mx = fmaxf(mx, m);
    }
    const unsigned tie = (cn > 1) ? 1u : 0u;
    g_mx[p]  = mx;
    g_amf[p] = (unsigned)am | (tie << 8);

    const int b = p / HWn;
    atomicAdd(&s_cnt[b * Cn + am], 1u);
    __syncthreads();
#pragma unroll
    for (int i = 0; i < NBIN / 256; ++i) {
        const unsigned c = s_cnt[threadIdx.x + i * 256];
        if (c) atomicAdd(&g_hist[threadIdx.x + i * 256], c);
    }
}

// ---------------- K3: exclusive scan of 1024 bins (one block) ----------------
__global__ void __launch_bounds__(NBIN)
scan_kernel() {
    __shared__ unsigned s[NBIN];
    const int i = threadIdx.x;
    s[i] = g_hist[i];
    __syncthreads();
    for (int d = 1; d < NBIN; d <<= 1) {
        unsigned add = (i >= d) ? s[i - d] : 0u;
        __syncthreads();
        s[i] += add;
        __syncthreads();
    }
    g_cursor[i] = s[i] - g_hist[i];
}

// ---------------- K4: scatter pixel ids into bin-sorted list -----------------
__global__ void __launch_bounds__(256)
scatter_kernel() {
    const int p = blockIdx.x * 256 + threadIdx.x;   // exact cover
    const unsigned amf = g_amf[p];
    const unsigned am  = amf & 0xFF;
    const unsigned tie = amf >> 8;
    const int b = p / HWn;
    const unsigned slot = atomicAdd(&g_cursor[b * Cn + am], 1u);
    g_list[slot] = (unsigned)p | (am << 18) | (tie << 26);
}

// Warp-cooperative 9x9 window max: lanes 0..26 each load one float4 of the
// 9-row x 12-col aligned span (1 warp-LDG for the whole window), mask invalid
// columns, then 5-step bfly reduce. All lanes return the window max.
__device__ __forceinline__ float warp_window_max(
    const float* __restrict__ chan, int h, int wa, int lo, int hi, int lane) {
    float nb = NEG_INF;
    if (lane < 27) {
        const int ri = lane / 3;          // window row 0..8
        const int cj = lane - 3 * ri;     // float4 index 0..2
        const int r = min(max(h - 4 + ri, 0), Hn - 1);  // clamp dup: max-safe
        const float4 v = __ldg(
            reinterpret_cast<const float4*>(chan + r * Wn + wa) + cj);
        const int c0 = wa + cj * 4;
        nb = fmaxf(nb, (c0 + 0 >= lo && c0 + 0 <= hi) ? v.x : NEG_INF);
        nb = fmaxf(nb, (c0 + 1 >= lo && c0 + 1 <= hi) ? v.y : NEG_INF);
        nb = fmaxf(nb, (c0 + 2 >= lo && c0 + 2 <= hi) ? v.z : NEG_INF);
        nb = fmaxf(nb, (c0 + 3 >= lo && c0 + 3 <= hi) ? v.w : NEG_INF);
    }
#pragma unroll
    for (int s = 16; s > 0; s >>= 1)
        nb = fmaxf(nb, __shfl_xor_sync(0xFFFFFFFFu, nb, s));
    return nb;
}

// ---------------- K5: warp-per-pixel bin-ordered gather ----------------------
__global__ void __launch_bounds__(256)
wgather_kernel(const float* __restrict__ x, float* __restrict__ out) {
    const int wix  = (blockIdx.x * 256 + threadIdx.x) >> 5;  // 0..NPIX-1 exact
    const int lane = threadIdx.x & 31;

    const unsigned e = g_list[wix];          // broadcast (same addr all lanes)
    const int p   = (int)(e & 0x3FFFFu);
    const int am  = (int)((e >> 18) & 0xFFu);
    const int tie = (int)(e >> 26);

    const int b  = p / HWn;
    const int rm = p - b * HWn;
    const int h  = rm / Wn;
    const int w  = rm - h * Wn;

    const float mx = g_mx[p];                // broadcast
    const float* __restrict__ xb = x + (size_t)b * CHWn;

    const int lo = w - 4;
    const int hi = w + 4;
    int wa = (w - 4) & ~3;
    if (wa < 0) wa = 0;
    if (wa > Wn - 12) wa = Wn - 12;          // 308, stays 16B-aligned

    float res;
    if (!tie) {
        const float nb = warp_window_max(xb + (size_t)am * HWn, h, wa, lo, hi, lane);
        res = (nb <= mx) ? mx : 0.0f;        // nb >= mx always (center incl.)
    } else {
        // Exact tie path (statistically ~0 pixels): warp-cooperative per
        // candidate channel; `v == mx` is warp-uniform (same address).
        int cnt = 0;
        for (int c = 0; c < Cn; ++c) {
            const float v = __ldg(xb + (size_t)c * HWn + rm);
            if (v == mx) {
                const float nb =
                    warp_window_max(xb + (size_t)c * HWn, h, wa, lo, hi, lane);
                if (nb <= mx) cnt++;
            }
        }
        res = mx * (float)cnt;
    }

    if (lane == 0) out[p] = res;             // exact cover: plain store
}

extern "C" void kernel_launch(void* const* d_in, const int* in_sizes, int n_in,
                              void* d_out, int out_size) {
    const float* x = (const float*)d_in[0];
    float* out = (float*)d_out;
    (void)in_sizes; (void)n_in; (void)out_size;

    phaseA_kernel<<<(CHUNKS * NGRP) / 256, 256>>>(x);   // 1000 blocks
    merge_count_kernel<<<NPIX / 256, 256>>>();          // 1000 blocks
    scan_kernel<<<1, NBIN>>>();
    scatter_kernel<<<NPIX / 256, 256>>>();              // 1000 blocks
    wgather_kernel<<<(NPIX * 32) / 256, 256>>>(x, out); // 32000 blocks
}

// round 17
// speedup vs baseline: 1.7759x; 1.1728x over previous
#include <cuda_runtime.h>
#include <math_constants.h>

// x[B=4, C=256, H=200, W=320] f32 -> out[B,H,W] f32
#define Bn 4
#define Cn 256
#define Hn 200
#define Wn 320
#define HWn (Hn * Wn)            // 64000
#define CHWn (Cn * HWn)          // 16384000
#define HW4 (HWn / 4)            // 16000
#define NPIX (Bn * HWn)          // 256000
#define NGRP (Bn * HW4)          // 64000

#define CHUNKS 4
#define CPC   (Cn / CHUNKS)      // 64

#define NEG_INF (-CUDART_INF_F)

// ---- scratch: per-chunk partials (written by phaseA, L2-resident) ----
__device__ float4 g_pmax[CHUNKS * NGRP];   // 4 MB
__device__ int4   g_pmeta[CHUNKS * NGRP];  // 4 MB

// ---------------- K1: channel-chunk partial depth-wise argmax ----------------
__global__ void __launch_bounds__(256)
phaseA_kernel(const float* __restrict__ x) {
    const int t = blockIdx.x * 256 + threadIdx.x;   // exact cover
    const int chunk = t / NGRP;
    const int gg    = t - chunk * NGRP;
    const int b     = gg / HW4;
    const int pg    = gg - b * HW4;

    const float4* __restrict__ src =
        reinterpret_cast<const float4*>(x + (size_t)b * CHWn
                                          + (size_t)chunk * CPC * HWn) + pg;

    float mx[4]; int am[4]; int cn[4];
#pragma unroll
    for (int k = 0; k < 4; ++k) { mx[k] = NEG_INF; am[k] = 0; cn[k] = 0; }

#pragma unroll 2
    for (int c0 = 0; c0 < CPC; c0 += 8) {
        float4 v[8];
#pragma unroll
        for (int j = 0; j < 8; ++j)
            v[j] = __ldg(src + (size_t)(c0 + j) * HW4);
#pragma unroll
        for (int j = 0; j < 8; ++j) {
            const float vv[4] = {v[j].x, v[j].y, v[j].z, v[j].w};
#pragma unroll
            for (int k = 0; k < 4; ++k) {
                const bool gt = vv[k] > mx[k];
                const bool eq = vv[k] == mx[k];
                cn[k] = gt ? 1 : (cn[k] + (eq ? 1 : 0));
                am[k] = gt ? (c0 + j) : am[k];
                mx[k] = fmaxf(mx[k], vv[k]);
            }
        }
    }

    g_pmax[t] = make_float4(mx[0], mx[1], mx[2], mx[3]);
    int4 meta;
    meta.x = (chunk * CPC + am[0]) | (cn[0] << 16);
    meta.y = (chunk * CPC + am[1]) | (cn[1] << 16);
    meta.z = (chunk * CPC + am[2]) | (cn[2] << 16);
    meta.w = (chunk * CPC + am[3]) | (cn[3] << 16);
    g_pmeta[t] = meta;
}

// Warp-cooperative 9x9 window max: lanes 0..26 each load one float4 of the
// 9-row x 12-col aligned span, mask invalid columns, 5-step bfly reduce.
// All lanes return the window max.
__device__ __forceinline__ float warp_window_max(
    const float* __restrict__ chan, int h, int wa, int lo, int hi, int lane) {
    float nb = NEG_INF;
    if (lane < 27) {
        const int ri = lane / 3;          // window row 0..8
        const int cj = lane - 3 * ri;     // float4 index 0..2
        const int r = min(max(h - 4 + ri, 0), Hn - 1);  // clamp dup: max-safe
        const float4 v = __ldg(
            reinterpret_cast<const float4*>(chan + r * Wn + wa) + cj);
        const int c0 = wa + cj * 4;
        nb = fmaxf(nb, (c0 + 0 >= lo && c0 + 0 <= hi) ? v.x : NEG_INF);
        nb = fmaxf(nb, (c0 + 1 >= lo && c0 + 1 <= hi) ? v.y : NEG_INF);
        nb = fmaxf(nb, (c0 + 2 >= lo && c0 + 2 <= hi) ? v.z : NEG_INF);
        nb = fmaxf(nb, (c0 + 3 >= lo && c0 + 3 <= hi) ? v.w : NEG_INF);
    }
#pragma unroll
    for (int s = 16; s > 0; s >>= 1)
        nb = fmaxf(nb, __shfl_xor_sync(0xFFFFFFFFu, nb, s));
    return nb;
}

// ---------------- K2: fused merge + warp-per-2-pixels gather -----------------
__global__ void __launch_bounds__(256)
wgather2_kernel(const float* __restrict__ x, float* __restrict__ out) {
    const int wix  = (blockIdx.x * 256 + threadIdx.x) >> 5;  // 0..NPIX/2-1
    const int lane = threadIdx.x & 31;
    const int p0 = wix * 2;
    const int p1 = p0 + 1;      // same batch as p0 (HWn even)

    const float* __restrict__ pmax  = reinterpret_cast<const float*>(g_pmax);
    const int*   __restrict__ pmeta = reinterpret_cast<const int*>(g_pmeta);

    // ---- in-warp merge of 4 chunk partials for both pixels (lanes 0..7) ----
    float m = NEG_INF; int meta = 0;
    if (lane < 8) {
        const int ch = lane & 3;
        const int pp = (lane >> 2) ? p1 : p0;
        m    = pmax[ch * NPIX + pp];
        meta = pmeta[ch * NPIX + pp];
    }
#pragma unroll
    for (int s = 1; s <= 2; s <<= 1) {
        const float om    = __shfl_xor_sync(0xFFFFFFFFu, m, s);
        const int   ometa = __shfl_xor_sync(0xFFFFFFFFu, meta, s);
        const bool gt = om > m;
        const bool eq = om == m;
        int cn = meta >> 16, am = meta & 0xFFFF;
        const int ocn = ometa >> 16, oam = ometa & 0xFFFF;
        cn = gt ? ocn : (cn + (eq ? ocn : 0));
        am = gt ? oam : am;
        m  = fmaxf(m, om);
        meta = am | (cn << 16);
    }
    const float mx0 = __shfl_sync(0xFFFFFFFFu, m, 0);
    const int   mt0 = __shfl_sync(0xFFFFFFFFu, meta, 0);
    const float mx1 = __shfl_sync(0xFFFFFFFFu, m, 4);
    const int   mt1 = __shfl_sync(0xFFFFFFFFu, meta, 4);
    const int am0 = mt0 & 0xFFFF, cn0 = mt0 >> 16;
    const int am1 = mt1 & 0xFFFF, cn1 = mt1 >> 16;

    // ---- geometry for both pixels ----
    const int b   = p0 / HWn;
    const int rm0 = p0 - b * HWn;
    const int h0 = rm0 / Wn, w0 = rm0 - h0 * Wn;
    const int rm1 = rm0 + 1;
    const int h1 = rm1 / Wn, w1 = rm1 - h1 * Wn;
    const float* __restrict__ xb = x + (size_t)b * CHWn;

    const int lo0 = w0 - 4, hi0 = w0 + 4;
    int wa0 = (w0 - 4) & ~3;
    wa0 = wa0 < 0 ? 0 : (wa0 > Wn - 12 ? Wn - 12 : wa0);
    const int lo1 = w1 - 4, hi1 = w1 + 4;
    int wa1 = (w1 - 4) & ~3;
    wa1 = wa1 < 0 ? 0 : (wa1 > Wn - 12 ? Wn - 12 : wa1);

    // ---- issue both window loads back-to-back (independent chains) ----
    const int ri = lane / 3;
    const int cj = lane - 3 * ri;
    float4 v0 = make_float4(NEG_INF, NEG_INF, NEG_INF, NEG_INF);
    float4 v1 = v0;
    int c00 = 0, c01 = 0;
    if (lane < 27) {
        const int r0 = min(max(h0 - 4 + ri, 0), Hn - 1);
        const int r1 = min(max(h1 - 4 + ri, 0), Hn - 1);
        v0 = __ldg(reinterpret_cast<const float4*>(
                 xb + (size_t)am0 * HWn + r0 * Wn + wa0) + cj);
        v1 = __ldg(reinterpret_cast<const float4*>(
                 xb + (size_t)am1 * HWn + r1 * Wn + wa1) + cj);
        c00 = wa0 + cj * 4;
        c01 = wa1 + cj * 4;
    }
    float nb0 = NEG_INF, nb1 = NEG_INF;
    if (lane < 27) {
        nb0 = fmaxf(nb0, (c00 + 0 >= lo0 && c00 + 0 <= hi0) ? v0.x : NEG_INF);
        nb0 = fmaxf(nb0, (c00 + 1 >= lo0 && c00 + 1 <= hi0) ? v0.y : NEG_INF);
        nb0 = fmaxf(nb0, (c00 + 2 >= lo0 && c00 + 2 <= hi0) ? v0.z : NEG_INF);
        nb0 = fmaxf(nb0, (c00 + 3 >= lo0 && c00 + 3 <= hi0) ? v0.w : NEG_INF);
        nb1 = fmaxf(nb1, (c01 + 0 >= lo1 && c01 + 0 <= hi1) ? v1.x : NEG_INF);
        nb1 = fmaxf(nb1, (c01 + 1 >= lo1 && c01 + 1 <= hi1) ? v1.y : NEG_INF);
        nb1 = fmaxf(nb1, (c01 + 2 >= lo1 && c01 + 2 <= hi1) ? v1.z : NEG_INF);
        nb1 = fmaxf(nb1, (c01 + 3 >= lo1 && c01 + 3 <= hi1) ? v1.w : NEG_INF);
    }
#pragma unroll
    for (int s = 16; s > 0; s >>= 1) {
        nb0 = fmaxf(nb0, __shfl_xor_sync(0xFFFFFFFFu, nb0, s));
        nb1 = fmaxf(nb1, __shfl_xor_sync(0xFFFFFFFFu, nb1, s));
    }

    // ---- results (tie path warp-cooperative, warp-uniform guards) ----
    float res0, res1;
    if (cn0 == 1) {
        res0 = (nb0 <= mx0) ? mx0 : 0.0f;    // nb0 >= mx0 always
    } else {
        int cnt = 0;
        for (int c = 0; c < Cn; ++c) {
            const float v = __ldg(xb + (size_t)c * HWn + rm0);
            if (v == mx0) {
                const float nb = warp_window_max(xb + (size_t)c * HWn,
                                                 h0, wa0, lo0, hi0, lane);
                if (nb <= mx0) cnt++;
            }
        }
        res0 = mx0 * (float)cnt;
    }
    if (cn1 == 1) {
        res1 = (nb1 <= mx1) ? mx1 : 0.0f;
    } else {
        int cnt = 0;
        for (int c = 0; c < Cn; ++c) {
            const float v = __ldg(xb + (size_t)c * HWn + rm1);
            if (v == mx1) {
                const float nb = warp_window_max(xb + (size_t)c * HWn,
                                                 h1, wa1, lo1, hi1, lane);
                if (nb <= mx1) cnt++;
            }
        }
        res1 = mx1 * (float)cnt;
    }

    if (lane == 0)
        *reinterpret_cast<float2*>(out + p0) = make_float2(res0, res1);
}

extern "C" void kernel_launch(void* const* d_in, const int* in_sizes, int n_in,
                              void* d_out, int out_size) {
    const float* x = (const float*)d_in[0];
    float* out = (float*)d_out;
    (void)in_sizes; (void)n_in; (void)out_size;

    phaseA_kernel<<<(CHUNKS * NGRP) / 256, 256>>>(x);       // 1000 blocks
    wgather2_kernel<<<(NPIX / 2 * 32) / 256, 256>>>(x, out); // 16000 blocks
}